// round 1
// baseline (speedup 1.0000x reference)
#include <cuda_runtime.h>
#include <cstddef>

#define NSEL      20000
#define NB        32      // batch
#define IP        128     // in planes
#define OP        32      // hidden planes
#define XS_PITCH  132     // 128 + 4 pad -> conflict-free strided-row access

__global__ __launch_bounds__(64)
void voxel_mlp_kernel(
    const float* __restrict__ x,       // [32, 20000, 128]
    const int*   __restrict__ vidx,    // [20000]
    const float* __restrict__ w0,      // [40000, 128, 32]
    const float* __restrict__ b0,      // [40000, 32]
    const float* __restrict__ w1,      // [40000, 32]
    const float* __restrict__ b1,      // [40000]
    float*       __restrict__ out)     // [32, 20000]
{
    __shared__ float xs[NB * XS_PITCH];   // 32 rows x 132 (16.9 KB)
    __shared__ float ws[IP * OP];         // 128 x 32      (16.4 KB)
    __shared__ float b0s[OP];
    __shared__ float w1s[OP];
    __shared__ float b1s;

    const int n  = blockIdx.x;
    const int t  = threadIdx.x;
    const int vi = vidx[n];

    // ---- stage x tile: 32 rows of 128 floats (coalesced float4) ----
    const float4* gx = (const float4*)x;
    #pragma unroll
    for (int s = 0; s < 16; ++s) {
        int q  = t + 64 * s;          // 0..1023
        int b  = q >> 5;              // row (batch)
        int c4 = q & 31;              // float4 within row
        float4 v = gx[(size_t)(b * NSEL + n) * (IP / 4) + c4];
        *(float4*)&xs[b * XS_PITCH + 4 * c4] = v;
    }

    // ---- stage gathered W0[vi]: 128x32 contiguous (coalesced float4) ----
    const float4* gw = (const float4*)w0 + (size_t)vi * (IP * OP / 4);
    #pragma unroll
    for (int s = 0; s < 16; ++s) {
        int q = t + 64 * s;           // 0..1023
        *(float4*)&ws[4 * q] = gw[q];
    }

    if (t < OP) {
        b0s[t] = b0[(size_t)vi * OP + t];
        w1s[t] = w1[(size_t)vi * OP + t];
    }
    if (t == 0) b1s = b1[vi];
    __syncthreads();

    // ---- register-tiled 32x32x128 GEMM: per-thread 4b x 4o ----
    const int og = t & 7;    // owns cols o = 4*og + c      (c = 0..3)
    const int bg = t >> 3;   // owns rows b = bg + 8*j      (j = 0..3)

    float acc[4][4];
    #pragma unroll
    for (int j = 0; j < 4; ++j)
        #pragma unroll
        for (int c = 0; c < 4; ++c) acc[j][c] = 0.f;

    #pragma unroll 4
    for (int ii = 0; ii < IP / 4; ++ii) {
        float4 xv[4];
        #pragma unroll
        for (int j = 0; j < 4; ++j)
            xv[j] = *(const float4*)&xs[(bg + 8 * j) * XS_PITCH + 4 * ii];

        #pragma unroll
        for (int k = 0; k < 4; ++k) {
            float4 wv = *(const float4*)&ws[(4 * ii + k) * OP + 4 * og];
            #pragma unroll
            for (int j = 0; j < 4; ++j) {
                float xjk = ((const float*)&xv[j])[k];
                acc[j][0] = fmaf(xjk, wv.x, acc[j][0]);
                acc[j][1] = fmaf(xjk, wv.y, acc[j][1]);
                acc[j][2] = fmaf(xjk, wv.z, acc[j][2]);
                acc[j][3] = fmaf(xjk, wv.w, acc[j][3]);
            }
        }
    }

    // ---- epilogue: scale, bias, exact-erf GELU, layer-1 projection ----
    const float inv128 = 0.0078125f;   // 1/128
    const float inv32  = 0.03125f;     // 1/32

    float partial[4];
    #pragma unroll
    for (int j = 0; j < 4; ++j) {
        float s = 0.f;
        #pragma unroll
        for (int c = 0; c < 4; ++c) {
            int   o = 4 * og + c;
            float v = acc[j][c] * inv128 + b0s[o];
            float g = 0.5f * v * (1.f + erff(v * 0.70710678118654752f));
            s = fmaf(g, w1s[o], s);
        }
        partial[j] = s;
    }

    // reduce over the 8 lanes sharing the same b-group (og bits = lane bits 0..2)
    #pragma unroll
    for (int off = 1; off < 8; off <<= 1) {
        #pragma unroll
        for (int j = 0; j < 4; ++j)
            partial[j] += __shfl_xor_sync(0xffffffffu, partial[j], off);
    }

    if (og == 0) {
        #pragma unroll
        for (int j = 0; j < 4; ++j) {
            int b = bg + 8 * j;
            out[(size_t)b * NSEL + n] = partial[j] * inv32 + b1s;
        }
    }
}

extern "C" void kernel_launch(void* const* d_in, const int* in_sizes, int n_in,
                              void* d_out, int out_size)
{
    const float* x    = (const float*)d_in[0];
    const int*   vidx = (const int*)  d_in[1];
    const float* w0   = (const float*)d_in[2];
    const float* b0   = (const float*)d_in[3];
    const float* w1   = (const float*)d_in[4];
    const float* b1   = (const float*)d_in[5];
    float* out = (float*)d_out;

    voxel_mlp_kernel<<<NSEL, 64>>>(x, vidx, w0, b0, w1, b1, out);
}

// round 2
// speedup vs baseline: 1.1366x; 1.1366x over previous
#include <cuda_runtime.h>
#include <cstddef>
#include <cstdint>

#define NSEL      20000
#define NB        32      // batch
#define IP        128     // in planes
#define OP        32      // hidden planes
#define XS_PITCH  132     // 128 + 4 pad floats -> conflict-free strided row access
#define NTHREADS  128

__device__ __forceinline__ uint32_t smem_u32(const void* p) {
    uint32_t a;
    asm("{ .reg .u64 t; cvta.to.shared.u64 t, %1; cvt.u32.u64 %0, t; }"
        : "=r"(a) : "l"(p));
    return a;
}
__device__ __forceinline__ void cp_async16(uint32_t dst, const void* src) {
    asm volatile("cp.async.cg.shared.global [%0], [%1], 16;\n" :: "r"(dst), "l"(src));
}
__device__ __forceinline__ void cp_async_commit() {
    asm volatile("cp.async.commit_group;\n" ::: "memory");
}
__device__ __forceinline__ void cp_async_wait0() {
    asm volatile("cp.async.wait_group 0;\n" ::: "memory");
}

__global__ __launch_bounds__(NTHREADS, 6)
void voxel_mlp_kernel(
    const float* __restrict__ x,       // [32, 20000, 128]
    const int*   __restrict__ vidx,    // [20000]
    const float* __restrict__ w0,      // [40000, 128, 32]
    const float* __restrict__ b0,      // [40000, 32]
    const float* __restrict__ w1,      // [40000, 32]
    const float* __restrict__ b1,      // [40000]
    float*       __restrict__ out)     // [32, 20000]
{
    __shared__ float xs[NB * XS_PITCH];   // 16.9 KB
    __shared__ float ws[IP * OP];         // 16.4 KB
    __shared__ float b0s[OP];
    __shared__ float w1s[OP];
    __shared__ float b1s;

    const int n  = blockIdx.x;
    const int t  = threadIdx.x;
    const int vi = vidx[n];

    // ---- stage x tile (32 x 128) via cp.async: 8 x 16B per thread ----
    const float4* gx = (const float4*)x;
    const uint32_t xs_base = smem_u32(xs);
    #pragma unroll
    for (int s = 0; s < 8; ++s) {
        int q  = t + NTHREADS * s;    // 0..1023
        int b  = q >> 5;              // batch row
        int c4 = q & 31;              // float4 within row
        cp_async16(xs_base + (b * XS_PITCH + 4 * c4) * 4,
                   gx + (size_t)(b * NSEL + n) * (IP / 4) + c4);
    }

    // ---- stage gathered W0[vi] (128 x 32 contiguous): 8 x 16B per thread ----
    const float4* gw = (const float4*)w0 + (size_t)vi * (IP * OP / 4);
    const uint32_t ws_base = smem_u32(ws);
    #pragma unroll
    for (int s = 0; s < 8; ++s) {
        int q = t + NTHREADS * s;     // 0..1023
        cp_async16(ws_base + 16 * q, gw + q);
    }
    cp_async_commit();

    if (t < OP) {
        b0s[t] = b0[(size_t)vi * OP + t];
        w1s[t] = w1[(size_t)vi * OP + t];
    }
    if (t == 0) b1s = b1[vi];

    cp_async_wait0();
    __syncthreads();

    // ---- register-tiled GEMM: per-thread 2 batch rows x 4 outputs ----
    const int og = t & 7;     // output group: cols o = 4*og + c
    const int bg = t >> 3;    // 0..15: rows bg and bg+16

    float acc[2][4];
    #pragma unroll
    for (int j = 0; j < 2; ++j)
        #pragma unroll
        for (int c = 0; c < 4; ++c) acc[j][c] = 0.f;

    #pragma unroll 4
    for (int ii = 0; ii < IP / 4; ++ii) {
        float4 xv[2];
        #pragma unroll
        for (int j = 0; j < 2; ++j)
            xv[j] = *(const float4*)&xs[(bg + 16 * j) * XS_PITCH + 4 * ii];

        #pragma unroll
        for (int k = 0; k < 4; ++k) {
            float4 wv = *(const float4*)&ws[(4 * ii + k) * OP + 4 * og];
            #pragma unroll
            for (int j = 0; j < 2; ++j) {
                float xjk = ((const float*)&xv[j])[k];
                acc[j][0] = fmaf(xjk, wv.x, acc[j][0]);
                acc[j][1] = fmaf(xjk, wv.y, acc[j][1]);
                acc[j][2] = fmaf(xjk, wv.z, acc[j][2]);
                acc[j][3] = fmaf(xjk, wv.w, acc[j][3]);
            }
        }
    }

    // ---- epilogue: scale, bias, exact-erf GELU, layer-1 projection ----
    const float inv128 = 0.0078125f;
    const float inv32  = 0.03125f;

    float partial[2];
    #pragma unroll
    for (int j = 0; j < 2; ++j) {
        float s = 0.f;
        #pragma unroll
        for (int c = 0; c < 4; ++c) {
            int   o = 4 * og + c;
            float v = acc[j][c] * inv128 + b0s[o];
            float g = 0.5f * v * (1.f + erff(v * 0.70710678118654752f));
            s = fmaf(g, w1s[o], s);
        }
        partial[j] = s;
    }

    // reduce across the 8 lanes sharing a b-group (og = lane bits 0..2)
    #pragma unroll
    for (int off = 1; off < 8; off <<= 1) {
        #pragma unroll
        for (int j = 0; j < 2; ++j)
            partial[j] += __shfl_xor_sync(0xffffffffu, partial[j], off);
    }

    if (og == 0) {
        #pragma unroll
        for (int j = 0; j < 2; ++j) {
            int b = bg + 16 * j;
            out[(size_t)b * NSEL + n] = partial[j] * inv32 + b1s;
        }
    }
}

extern "C" void kernel_launch(void* const* d_in, const int* in_sizes, int n_in,
                              void* d_out, int out_size)
{
    const float* x    = (const float*)d_in[0];
    const int*   vidx = (const int*)  d_in[1];
    const float* w0   = (const float*)d_in[2];
    const float* b0   = (const float*)d_in[3];
    const float* w1   = (const float*)d_in[4];
    const float* b1   = (const float*)d_in[5];
    float* out = (float*)d_out;

    voxel_mlp_kernel<<<NSEL, NTHREADS>>>(x, vidx, w0, b0, w1, b1, out);
}

// round 3
// speedup vs baseline: 1.5978x; 1.4057x over previous
#include <cuda_runtime.h>
#include <cstddef>
#include <cstdint>

#define NSEL      20000
#define NB        32      // batch
#define IP        128     // in planes
#define OP        32      // hidden planes
#define CK        32      // K-chunk (floats)
#define NCHUNK    (IP / CK)          // 4
#define XP        36      // xs chunk pitch (floats): 36 mod 32 = 4 -> conflict-free
#define NTHREADS  64

__device__ __forceinline__ uint32_t smem_u32(const void* p) {
    uint32_t a;
    asm("{ .reg .u64 t; cvta.to.shared.u64 t, %1; cvt.u32.u64 %0, t; }"
        : "=r"(a) : "l"(p));
    return a;
}
__device__ __forceinline__ void cp_async16(uint32_t dst, const void* src) {
    asm volatile("cp.async.cg.shared.global [%0], [%1], 16;\n" :: "r"(dst), "l"(src));
}
__device__ __forceinline__ void cp_async_commit() {
    asm volatile("cp.async.commit_group;\n" ::: "memory");
}
template <int N>
__device__ __forceinline__ void cp_async_wait() {
    asm volatile("cp.async.wait_group %0;\n" :: "n"(N) : "memory");
}

__global__ __launch_bounds__(NTHREADS, 12)
void voxel_mlp_kernel(
    const float* __restrict__ x,       // [32, 20000, 128]
    const int*   __restrict__ vidx,    // [20000]
    const float* __restrict__ w0,      // [40000, 128, 32]
    const float* __restrict__ b0,      // [40000, 32]
    const float* __restrict__ w1,      // [40000, 32]
    const float* __restrict__ b1,      // [40000]
    float*       __restrict__ out)     // [32, 20000]
{
    // double-buffered K-chunks
    __shared__ float xs[2][NB * XP];        // 2 * 32*36*4 = 9.2 KB
    __shared__ float ws[2][CK * OP];        // 2 * 32*32*4 = 8.0 KB
    __shared__ float b0s[OP];
    __shared__ float w1s[OP];
    __shared__ float b1s;

    const int n  = blockIdx.x;
    const int t  = threadIdx.x;
    const int vi = vidx[n];

    const float4* gx = (const float4*)x;                       // [b][n][32 f4]
    const float4* gw = (const float4*)w0 + (size_t)vi * (IP * OP / 4);

    const uint32_t xs_base = smem_u32(xs);
    const uint32_t ws_base = smem_u32(ws);

    // per-chunk staging: 256 f4 of x + 256 f4 of w -> 4+4 cp.async per thread
    auto load_chunk = [&](int c, int buf) {
        #pragma unroll
        for (int s = 0; s < 4; ++s) {
            int q  = t + NTHREADS * s;        // 0..255
            int b  = q >> 3;                  // batch row
            int f4 = q & 7;                   // float4 within chunk row
            cp_async16(xs_base + (uint32_t)(buf * NB * XP + b * XP + 4 * f4) * 4,
                       gx + (size_t)(b * NSEL + n) * (IP / 4) + c * (CK / 4) + f4);
        }
        #pragma unroll
        for (int s = 0; s < 4; ++s) {
            int q = t + NTHREADS * s;         // 0..255
            cp_async16(ws_base + (uint32_t)(buf * CK * OP + 4 * q) * 4,
                       gw + c * (CK * OP / 4) + q);
        }
        cp_async_commit();
    };

    load_chunk(0, 0);

    if (t < OP) {
        b0s[t] = b0[(size_t)vi * OP + t];
        w1s[t] = w1[(size_t)vi * OP + t];
    }
    if (t == 0) b1s = b1[vi];

    // ---- register tile: 4 batch rows x 4 outputs per thread ----
    const int og = t & 7;    // cols o = 4*og + c
    const int bg = t >> 3;   // rows b = bg + 8*j

    float acc[4][4];
    #pragma unroll
    for (int j = 0; j < 4; ++j)
        #pragma unroll
        for (int c = 0; c < 4; ++c) acc[j][c] = 0.f;

    #pragma unroll
    for (int ch = 0; ch < NCHUNK; ++ch) {
        const int buf = ch & 1;
        if (ch + 1 < NCHUNK) {
            load_chunk(ch + 1, buf ^ 1);
            cp_async_wait<1>();
        } else {
            cp_async_wait<0>();
        }
        __syncthreads();

        const float* xb = &xs[buf][0];
        const float* wb = &ws[buf][0];

        #pragma unroll
        for (int ii = 0; ii < CK / 4; ++ii) {
            float4 xv[4];
            #pragma unroll
            for (int j = 0; j < 4; ++j)
                xv[j] = *(const float4*)&xb[(bg + 8 * j) * XP + 4 * ii];

            #pragma unroll
            for (int k = 0; k < 4; ++k) {
                float4 wv = *(const float4*)&wb[(4 * ii + k) * OP + 4 * og];
                #pragma unroll
                for (int j = 0; j < 4; ++j) {
                    float xjk = ((const float*)&xv[j])[k];
                    acc[j][0] = fmaf(xjk, wv.x, acc[j][0]);
                    acc[j][1] = fmaf(xjk, wv.y, acc[j][1]);
                    acc[j][2] = fmaf(xjk, wv.z, acc[j][2]);
                    acc[j][3] = fmaf(xjk, wv.w, acc[j][3]);
                }
            }
        }
        __syncthreads();   // all reads of buf done before it is refilled
    }

    // ---- epilogue: scale, bias, exact-erf GELU, layer-1 projection ----
    const float inv128 = 0.0078125f;
    const float inv32  = 0.03125f;

    float partial[4];
    #pragma unroll
    for (int j = 0; j < 4; ++j) {
        float s = 0.f;
        #pragma unroll
        for (int c = 0; c < 4; ++c) {
            int   o = 4 * og + c;
            float v = acc[j][c] * inv128 + b0s[o];
            float g = 0.5f * v * (1.f + erff(v * 0.70710678118654752f));
            s = fmaf(g, w1s[o], s);
        }
        partial[j] = s;
    }

    // reduce across the 8 lanes sharing a b-group (og = lane bits 0..2)
    #pragma unroll
    for (int off = 1; off < 8; off <<= 1) {
        #pragma unroll
        for (int j = 0; j < 4; ++j)
            partial[j] += __shfl_xor_sync(0xffffffffu, partial[j], off);
    }

    if (og == 0) {
        #pragma unroll
        for (int j = 0; j < 4; ++j) {
            int b = bg + 8 * j;
            out[(size_t)b * NSEL + n] = partial[j] * inv32 + b1s;
        }
    }
}

extern "C" void kernel_launch(void* const* d_in, const int* in_sizes, int n_in,
                              void* d_out, int out_size)
{
    const float* x    = (const float*)d_in[0];
    const int*   vidx = (const int*)  d_in[1];
    const float* w0   = (const float*)d_in[2];
    const float* b0   = (const float*)d_in[3];
    const float* w1   = (const float*)d_in[4];
    const float* b1   = (const float*)d_in[5];
    float* out = (float*)d_out;

    voxel_mlp_kernel<<<NSEL, NTHREADS>>>(x, vidx, w0, b0, w1, b1, out);
}